// round 10
// baseline (speedup 1.0000x reference)
#include <cuda_runtime.h>
#include <cstddef>

#define LCH   4096
#define BATCH 4096
#define SEG   32
#define NSEG  128

// M_o[k][l] = psi[k,l]*phi_o[l]: one 2x2 per obs value; phi kept for beliefs.
struct Pots { float pA0, pA1, pB0, pB1;
              float4 M0, M1; };

__device__ __forceinline__ Pots make_pots(const float* jp, const float* bp) {
    Pots P;
    float j = jp[0], b0 = bp[0], b1 = bp[1];
    float pd = expf( 0.25f * j);
    float po = expf(-0.25f * j);
    P.pA0 = expf(-0.5f * b0);  P.pA1 = expf(0.5f * b0);
    P.pB0 = expf(-0.5f * b1);  P.pB1 = expf(0.5f * b1);
    P.M0 = make_float4(pd * P.pA0, po * P.pA1, po * P.pA0, pd * P.pA1);
    P.M1 = make_float4(pd * P.pB0, po * P.pB1, po * P.pB0, pd * P.pB1);
    return P;
}

// (max,*) 2x2 matrix product: C = A x B.  layout x=m00 y=m01 z=m10 w=m11
__device__ __forceinline__ float4 mm(float4 A, float4 B) {
    return make_float4(
        fmaxf(A.x * B.x, A.y * B.z), fmaxf(A.x * B.y, A.y * B.w),
        fmaxf(A.z * B.x, A.w * B.z), fmaxf(A.z * B.y, A.w * B.w));
}

__device__ __forceinline__ float4 shflup4(float4 v, int d) {
    v.x = __shfl_up_sync(0xffffffffu, v.x, d);
    v.y = __shfl_up_sync(0xffffffffu, v.y, d);
    v.z = __shfl_up_sync(0xffffffffu, v.z, d);
    v.w = __shfl_up_sync(0xffffffffu, v.w, d);
    return v;
}
__device__ __forceinline__ float4 shfldn4(float4 v, int d) {
    v.x = __shfl_down_sync(0xffffffffu, v.x, d);
    v.y = __shfl_down_sync(0xffffffffu, v.y, d);
    v.z = __shfl_down_sync(0xffffffffu, v.z, d);
    v.w = __shfl_down_sync(0xffffffffu, v.w, d);
    return v;
}

// ---------------------------------------------------------------------------
// One block per row. Both message chains broken into 8 independent chunks
// via prefix products PP[g] (fwd) and suffix products SS[g] (bwd); per-step
// latency reduced to FMUL->FMAX via folded M matrices.
// ---------------------------------------------------------------------------
__global__ void __launch_bounds__(128, 3)
fused(const float* __restrict__ jp, const float* __restrict__ bp,
      const int* __restrict__ obs, float* __restrict__ out)
{
    const int t = threadIdx.x, b = blockIdx.x;
    const int lane = t & 31, warp = t >> 5;

    __shared__ unsigned char smNib[1024];
    __shared__ float4 lutP[16], lutQ[16];
    __shared__ float4 wTotP[4], wTotQ[4];
    __shared__ float  smo[2 * LCH];         // 32 KB output stage
    float4* sm4 = reinterpret_cast<float4*>(smo);

    const Pots pt = make_pots(jp, bp);

    // ---- obs -> nibbles (coalesced int4 loads) ----
    const int4* row4 = reinterpret_cast<const int4*>(obs + (size_t)b * LCH);
#pragma unroll
    for (int q = 0; q < 8; q++) {
        int  eq = q * 128 + t;
        int4 v  = row4[eq];
        smNib[eq] = (unsigned char)((v.x & 1) | ((v.y & 1) << 1) |
                                    ((v.z & 1) << 2) | ((v.w & 1) << 3));
    }

    // ---- 4-bit LUTs of 4-step transfer matrices (M-form) ----
    if (t < 16) {
        float4 Pm = make_float4(1.f, 0.f, 0.f, 1.f);
        float4 Qm = make_float4(1.f, 0.f, 0.f, 1.f);
#pragma unroll
        for (int i = 0; i < 4; i++) {
            float4 M = ((t >> i) & 1) ? pt.M1 : pt.M0;
            Pm = mm(M, Pm);          // applied-after (left compose)
            Qm = mm(Qm, M);          // position order (right compose)
        }
        lutP[t] = Pm;
        lutQ[t] = Qm;
    }
    __syncthreads();

    // ---- assemble 32-bit mask for segment t ----
    uint2 nb = reinterpret_cast<const uint2*>(smNib)[t];
    unsigned lo   = nb.x | (nb.x >> 4);
    unsigned lo16 = (lo & 0xFFu) | ((lo >> 8) & 0xFF00u);
    unsigned hi   = nb.y | (nb.y >> 4);
    unsigned hi16 = (hi & 0xFFu) | ((hi >> 8) & 0xFF00u);
    const unsigned bits = lo16 | (hi16 << 16);

    // ---- prefix products PP[g] (fwd) and suffix products SS[g] (bwd) ----
    float4 PP[8];                 // PP[g] = chunkP_{g-1} o ... o chunkP_0 ; PP[0]=I
    float4 P = make_float4(1.f, 0.f, 0.f, 1.f);
#pragma unroll
    for (int c = 0; c < 8; c++) {
        PP[c] = P;
        P = mm(lutP[(bits >> (4 * c)) & 15u], P);
    }
    // P = full segment forward matrix

    float4 SS[8];                 // SS[g] = chunkQ_{g+1} . ... . chunkQ_7 ; SS[7]=I
    float4 Q = make_float4(1.f, 0.f, 0.f, 1.f);
#pragma unroll
    for (int c = 7; c >= 0; c--) {
        SS[c] = Q;
        Q = mm(lutQ[(bits >> (4 * c)) & 15u], Q);
    }
    // Q = full segment backward matrix

    // ---- block scan: forward prefix of P, backward suffix of Q ----
    float4 sp = P;
#pragma unroll
    for (int d = 1; d < 32; d <<= 1) {
        float4 o = shflup4(sp, d);
        if (lane >= d) sp = mm(sp, o);
    }
    if (lane == 31) wTotP[warp] = sp;

    float4 sq = Q;
#pragma unroll
    for (int d = 1; d < 32; d <<= 1) {
        float4 o = shfldn4(sq, d);
        if (lane + d < 32) sq = mm(sq, o);
    }
    if (lane == 0) wTotQ[warp] = sq;
    __syncthreads();

    float4 prefP = make_float4(1.f, 0.f, 0.f, 1.f);
#pragma unroll
    for (int k = 2; k >= 0; k--)
        if (warp > k) prefP = mm(prefP, wTotP[k]);

    float4 sufQ = make_float4(1.f, 0.f, 0.f, 1.f);
#pragma unroll
    for (int k = 1; k < 4; k++)
        if (warp < k) sufQ = mm(sufQ, wTotQ[k]);

    float4 exP = shflup4(sp, 1);
    if (lane == 0) exP = make_float4(1.f, 0.f, 0.f, 1.f);
    exP = mm(exP, prefP);
    const float fs0 = fmaxf(exP.x, exP.y), fs1 = fmaxf(exP.z, exP.w); // fwd msg @ seg start

    float4 exQ = shfldn4(sq, 1);
    if (lane == 31) exQ = make_float4(1.f, 0.f, 0.f, 1.f);
    exQ = mm(exQ, sufQ);
    const float g0 = fmaxf(exQ.x, exQ.y), g1 = fmaxf(exQ.z, exQ.w);  // bwd msg @ seg end

    // ---- fused sweep: every chunk independent in both directions ----
    const int xr = t & 7;
#pragma unroll
    for (int gg = 0; gg < 8; gg++) {
        // backward msgs within chunk from suffix product (3 local steps)
        float bb0[4], bb1[4];
        bb0[3] = fmaxf(SS[gg].x * g0, SS[gg].y * g1);
        bb1[3] = fmaxf(SS[gg].z * g0, SS[gg].w * g1);
#pragma unroll
        for (int u = 2; u >= 0; u--) {
            int    i = gg * 4 + u;
            float4 M = ((bits >> (i + 1)) & 1) ? pt.M1 : pt.M0;
            bb0[u] = fmaxf(M.x * bb0[u + 1], M.y * bb1[u + 1]);
            bb1[u] = fmaxf(M.z * bb0[u + 1], M.w * bb1[u + 1]);
        }
        // forward msg at chunk start from prefix product
        float f0 = fmaxf(PP[gg].x * fs0, PP[gg].y * fs1);
        float f1 = fmaxf(PP[gg].z * fs0, PP[gg].w * fs1);

        float v0[4], v1[4];
#pragma unroll
        for (int u = 0; u < 4; u++) {
            int   i  = gg * 4 + u;
            int   o  = (bits >> i) & 1;
            float p0 = o ? pt.pB0 : pt.pA0;
            float p1 = o ? pt.pB1 : pt.pA1;
            v0[u] = p0 * f0 * bb0[u];
            v1[u] = p1 * f1 * bb1[u];
            float4 M = o ? pt.M1 : pt.M0;
            float nf0 = fmaxf(M.x * f0, M.y * f1);
            float nf1 = fmaxf(M.z * f0, M.w * f1);
            f0 = nf0; f1 = nf1;
        }
        sm4[(t * 8 + gg) ^ xr]        = make_float4(v0[0], v0[1], v0[2], v0[3]);
        sm4[(1024 + t * 8 + gg) ^ xr] = make_float4(v1[0], v1[1], v1[2], v1[3]);
    }
    __syncthreads();

    // ---- single LDS pass + fully-coalesced store: out[b][k][t] ----
    float4* out4 = reinterpret_cast<float4*>(out) + (size_t)b * 2048;
#pragma unroll
    for (int r = 0; r < 16; r++) {
        int w4 = r * 128 + t;
        int x  = (w4 >> 3) & 7;
        out4[w4] = sm4[w4 ^ x];
    }
}

// ---------------------------------------------------------------------------
extern "C" void kernel_launch(void* const* d_in, const int* in_sizes, int n_in,
                              void* d_out, int out_size)
{
    const float* jp  = nullptr;
    const float* bp  = nullptr;
    const int*   obs = nullptr;
    for (int i = 0; i < n_in; i++) {
        if (in_sizes[i] == 1)      jp  = (const float*)d_in[i];
        else if (in_sizes[i] == 2) bp  = (const float*)d_in[i];
        else                       obs = (const int*)d_in[i];
    }
    float* out = (float*)d_out;

    fused<<<BATCH, 128>>>(jp, bp, obs, out);
}

// round 11
// speedup vs baseline: 1.1277x; 1.1277x over previous
#include <cuda_runtime.h>
#include <cstddef>

#define LCH   4096
#define BATCH 4096
#define SEG   32
#define NSEG  128

// M_o[k][l] = psi[k,l]*phi_o[l]; phi kept separately for belief multiply.
struct Pots { float pA0, pA1, pB0, pB1; float4 M0, M1; };

__device__ __forceinline__ Pots make_pots(const float* jp, const float* bp) {
    Pots P;
    float j = jp[0], b0 = bp[0], b1 = bp[1];
    float pd = expf( 0.25f * j);
    float po = expf(-0.25f * j);
    P.pA0 = expf(-0.5f * b0);  P.pA1 = expf(0.5f * b0);
    P.pB0 = expf(-0.5f * b1);  P.pB1 = expf(0.5f * b1);
    P.M0 = make_float4(pd * P.pA0, po * P.pA1, po * P.pA0, pd * P.pA1);
    P.M1 = make_float4(pd * P.pB0, po * P.pB1, po * P.pB0, pd * P.pB1);
    return P;
}

// (max,*) 2x2 matrix product: C = A x B.  layout x=m00 y=m01 z=m10 w=m11
__device__ __forceinline__ float4 mm(float4 A, float4 B) {
    return make_float4(
        fmaxf(A.x * B.x, A.y * B.z), fmaxf(A.x * B.y, A.y * B.w),
        fmaxf(A.z * B.x, A.w * B.z), fmaxf(A.z * B.y, A.w * B.w));
}

__device__ __forceinline__ float4 shflup4(float4 v, int d) {
    v.x = __shfl_up_sync(0xffffffffu, v.x, d);
    v.y = __shfl_up_sync(0xffffffffu, v.y, d);
    v.z = __shfl_up_sync(0xffffffffu, v.z, d);
    v.w = __shfl_up_sync(0xffffffffu, v.w, d);
    return v;
}
__device__ __forceinline__ float4 shfldn4(float4 v, int d) {
    v.x = __shfl_down_sync(0xffffffffu, v.x, d);
    v.y = __shfl_down_sync(0xffffffffu, v.y, d);
    v.z = __shfl_down_sync(0xffffffffu, v.z, d);
    v.w = __shfl_down_sync(0xffffffffu, v.w, d);
    return v;
}

// ---------------------------------------------------------------------------
// R9 structure: backward chain broken into 8 chunks via SS[g]; forward chain
// serial but with M-form steps (FMUL->FMAX, 8cyc instead of 12cyc).
// ---------------------------------------------------------------------------
__global__ void __launch_bounds__(128, 4)
fused(const float* __restrict__ jp, const float* __restrict__ bp,
      const int* __restrict__ obs, float* __restrict__ out)
{
    const int t = threadIdx.x, b = blockIdx.x;
    const int lane = t & 31, warp = t >> 5;

    __shared__ unsigned char smNib[1024];
    __shared__ float4 lutP[16], lutQ[16];
    __shared__ float4 wTotP[4], wTotQ[4];
    __shared__ float  smo[2 * LCH];         // 32 KB output stage
    float4* sm4 = reinterpret_cast<float4*>(smo);

    const Pots pt = make_pots(jp, bp);

    // ---- obs -> nibbles (coalesced int4 loads) ----
    const int4* row4 = reinterpret_cast<const int4*>(obs + (size_t)b * LCH);
#pragma unroll
    for (int q = 0; q < 8; q++) {
        int  eq = q * 128 + t;
        int4 v  = row4[eq];
        smNib[eq] = (unsigned char)((v.x & 1) | ((v.y & 1) << 1) |
                                    ((v.z & 1) << 2) | ((v.w & 1) << 3));
    }

    // ---- 4-bit LUTs of 4-step transfer matrices (M-form) ----
    if (t < 16) {
        float4 Pm = make_float4(1.f, 0.f, 0.f, 1.f);
        float4 Qm = make_float4(1.f, 0.f, 0.f, 1.f);
#pragma unroll
        for (int i = 0; i < 4; i++) {
            float4 M = ((t >> i) & 1) ? pt.M1 : pt.M0;
            Pm = mm(M, Pm);          // applied-after (left compose)
            Qm = mm(Qm, M);          // position order (right compose)
        }
        lutP[t] = Pm;
        lutQ[t] = Qm;
    }
    __syncthreads();

    // ---- assemble 32-bit mask for segment t ----
    uint2 nb = reinterpret_cast<const uint2*>(smNib)[t];
    unsigned lo   = nb.x | (nb.x >> 4);
    unsigned lo16 = (lo & 0xFFu) | ((lo >> 8) & 0xFF00u);
    unsigned hi   = nb.y | (nb.y >> 4);
    unsigned hi16 = (hi & 0xFFu) | ((hi >> 8) & 0xFF00u);
    const unsigned bits = lo16 | (hi16 << 16);

    // ---- P total (fwd) and Q suffix products SS[g] (bwd chain breaker) ----
    float4 P = lutP[bits & 15];
#pragma unroll
    for (int c = 1; c < 8; c++)
        P = mm(lutP[(bits >> (4 * c)) & 15u], P);

    float4 SS[8];                 // SS[g] = chunkQ_{g+1} . ... . chunkQ_7 ; SS[7]=I
    float4 Q = make_float4(1.f, 0.f, 0.f, 1.f);
#pragma unroll
    for (int c = 7; c >= 0; c--) {
        SS[c] = Q;
        Q = mm(lutQ[(bits >> (4 * c)) & 15u], Q);
    }
    // Q = full segment backward matrix

    // ---- block scan: forward prefix of P, backward suffix of Q ----
    float4 sp = P;
#pragma unroll
    for (int d = 1; d < 32; d <<= 1) {
        float4 o = shflup4(sp, d);
        if (lane >= d) sp = mm(sp, o);
    }
    if (lane == 31) wTotP[warp] = sp;

    float4 sq = Q;
#pragma unroll
    for (int d = 1; d < 32; d <<= 1) {
        float4 o = shfldn4(sq, d);
        if (lane + d < 32) sq = mm(sq, o);
    }
    if (lane == 0) wTotQ[warp] = sq;
    __syncthreads();

    float4 prefP = make_float4(1.f, 0.f, 0.f, 1.f);
#pragma unroll
    for (int k = 2; k >= 0; k--)
        if (warp > k) prefP = mm(prefP, wTotP[k]);

    float4 sufQ = make_float4(1.f, 0.f, 0.f, 1.f);
#pragma unroll
    for (int k = 1; k < 4; k++)
        if (warp < k) sufQ = mm(sufQ, wTotQ[k]);

    float4 exP = shflup4(sp, 1);
    if (lane == 0) exP = make_float4(1.f, 0.f, 0.f, 1.f);
    exP = mm(exP, prefP);
    float f0 = fmaxf(exP.x, exP.y), f1 = fmaxf(exP.z, exP.w);   // fwd msg @ seg start

    float4 exQ = shfldn4(sq, 1);
    if (lane == 31) exQ = make_float4(1.f, 0.f, 0.f, 1.f);
    exQ = mm(exQ, sufQ);
    const float g0 = fmaxf(exQ.x, exQ.y), g1 = fmaxf(exQ.z, exQ.w); // bwd msg @ seg end

    // ---- fused sweep: bwd msgs per chunk from SS[g]; fwd carried serially
    //      with M-form steps; beliefs written once ----
    const int xr = t & 7;
#pragma unroll
    for (int gg = 0; gg < 8; gg++) {
        // b at chunk end (position 4gg+3) directly from suffix product
        float bb0[4], bb1[4];
        bb0[3] = fmaxf(SS[gg].x * g0, SS[gg].y * g1);
        bb1[3] = fmaxf(SS[gg].z * g0, SS[gg].w * g1);
#pragma unroll
        for (int u = 2; u >= 0; u--) {
            int    i = gg * 4 + u;
            float4 M = ((bits >> (i + 1)) & 1) ? pt.M1 : pt.M0;
            bb0[u] = fmaxf(M.x * bb0[u + 1], M.y * bb1[u + 1]);
            bb1[u] = fmaxf(M.z * bb0[u + 1], M.w * bb1[u + 1]);
        }
        float v0[4], v1[4];
#pragma unroll
        for (int u = 0; u < 4; u++) {
            int   i  = gg * 4 + u;
            int   o  = (bits >> i) & 1;
            float p0 = o ? pt.pB0 : pt.pA0;
            float p1 = o ? pt.pB1 : pt.pA1;
            v0[u] = p0 * f0 * bb0[u];
            v1[u] = p1 * f1 * bb1[u];
            float4 M = o ? pt.M1 : pt.M0;
            float nf0 = fmaxf(M.x * f0, M.y * f1);
            float nf1 = fmaxf(M.z * f0, M.w * f1);
            f0 = nf0; f1 = nf1;
        }
        sm4[(t * 8 + gg) ^ xr]        = make_float4(v0[0], v0[1], v0[2], v0[3]);
        sm4[(1024 + t * 8 + gg) ^ xr] = make_float4(v1[0], v1[1], v1[2], v1[3]);
    }
    __syncthreads();

    // ---- single LDS pass + fully-coalesced store: out[b][k][t] ----
    float4* out4 = reinterpret_cast<float4*>(out) + (size_t)b * 2048;
#pragma unroll
    for (int r = 0; r < 16; r++) {
        int w4 = r * 128 + t;
        int x  = (w4 >> 3) & 7;
        out4[w4] = sm4[w4 ^ x];
    }
}

// ---------------------------------------------------------------------------
extern "C" void kernel_launch(void* const* d_in, const int* in_sizes, int n_in,
                              void* d_out, int out_size)
{
    const float* jp  = nullptr;
    const float* bp  = nullptr;
    const int*   obs = nullptr;
    for (int i = 0; i < n_in; i++) {
        if (in_sizes[i] == 1)      jp  = (const float*)d_in[i];
        else if (in_sizes[i] == 2) bp  = (const float*)d_in[i];
        else                       obs = (const int*)d_in[i];
    }
    float* out = (float*)d_out;

    fused<<<BATCH, 128>>>(jp, bp, obs, out);
}